// round 8
// baseline (speedup 1.0000x reference)
#include <cuda_runtime.h>
#include <cstdint>

#define NB    2
#define NTT   2
#define NLG   256
#define TT    64
#define SS    256
#define NVV   4
#define FF    16
#define KNN   3
#define CUTOFF   1e-3f
#define MASKVAL  1e6f

#define CAP   10            // pool capacity per (t, chunk)
#define PVS   82            // poolv stride per t (floats), 8*CAP=80 + pad
#define PSS   82            // poolsb stride per t (ushorts)

#define BIGV 3.4e38f
#define BIGI 0x3fffffff

__device__ __forceinline__ bool lessvi(float v, int i, float w, int j) {
    return (v < w) || (v == w && i < j);
}

// exact lexicographic (value, index) top-3 insert
__device__ __forceinline__ void top3_insert_vi(float v, int s,
                                               float& d0, float& d1, float& d2,
                                               int& i0, int& i1, int& i2) {
    if (lessvi(v, s, d2, i2)) {
        if (lessvi(v, s, d1, i1)) {
            d2 = d1; i2 = i1;
            if (lessvi(v, s, d0, i0)) { d1 = d0; i1 = i0; d0 = v; i0 = s; }
            else                      { d1 = v;  i1 = s; }
        } else {
            d2 = v; i2 = s;
        }
    }
}

__global__ __launch_bounds__(256, 5) void interp_kernel(
    const float* __restrict__ x,            // (B,NT, NL*S, NV, F)
    const void*  __restrict__ mask_raw,     // (B,NT, NL*S, NV) — dtype detected
    const float* __restrict__ dist,         // (B, NL, T, S)
    float* __restrict__ out)
{
    __shared__ float          poolv [32 * PVS];   // 10.5 KB candidate values
    __shared__ unsigned short poolsb[32 * PSS];   // 5.2 KB  s | nibble<<8
    __shared__ unsigned char  mnib  [SS];         // 256 B mask nibbles per s
    __shared__ unsigned char  cnts  [32 * 8];     // raw counts (may exceed CAP)
    __shared__ int s_flags[2];

    const int bid   = blockIdx.x;
    const int tb    = bid & 1;               // half of the 64 targets
    const int group = bid >> 1;
    const int l     = group & 255;
    const int nt    = (group >> 8) & 1;
    const int b     = group >> 9;
    const int tid   = threadIdx.x;

    if (tid == 0) { s_flags[0] = 0; s_flags[1] = 0; }
    __syncthreads();

    // ---- mask dtype detection from first 1024 bytes ----
    {
        const uchar4* mb = (const uchar4*)mask_raw;
        uchar4 q = mb[tid];
        int u8  = (q.y == 1) | (q.z == 1) | (q.w == 1);
        int f32 = (q.x == 0x3F) | (q.y == 0x3F) | (q.z == 0x3F) | (q.w == 0x3F);
        if (u8)  atomicOr(&s_flags[0], 1);
        if (f32) atomicOr(&s_flags[1], 1);
    }
    __syncthreads();
    const int mkind = s_flags[0] ? 0 : (s_flags[1] ? 2 : 1);

    // ---- stage mask -> nibble table mnib[s], bit nv set = masked ----
    {
        const size_t moff = ((size_t)((b * NTT + nt) * NLG + l)) * SS * NVV;
        int nib;
        if (mkind == 0) {            // uint8
            const uchar4* msrc = (const uchar4*)((const unsigned char*)mask_raw + moff);
            uchar4 m = msrc[tid];
            nib = (m.x ? 1 : 0) | (m.y ? 2 : 0) | (m.z ? 4 : 0) | (m.w ? 8 : 0);
        } else if (mkind == 1) {     // int32
            const int4* msrc = (const int4*)((const int*)mask_raw + moff);
            int4 m = msrc[tid];
            nib = (m.x ? 1 : 0) | (m.y ? 2 : 0) | (m.z ? 4 : 0) | (m.w ? 8 : 0);
        } else {                     // float32 0/1
            const float4* msrc = (const float4*)((const float*)mask_raw + moff);
            float4 m = msrc[tid];
            nib = (m.x != 0.0f ? 1 : 0) | (m.y != 0.0f ? 2 : 0) |
                  (m.z != 0.0f ? 4 : 0) | (m.w != 0.0f ? 8 : 0);
        }
        mnib[tid] = (unsigned char)nib;
    }
    __syncthreads();

    // ================= Phase A: threshold + compaction (global reads) ======
    // lane = (t: tid>>3, chunk c: tid&7); chunk covers s in [32c, 32c+32)
    const int at = tid >> 3;
    const int ac = tid & 7;
    const float* dptr = dist + (((size_t)(b * NLG + l)) * TT + tb * 32) * SS;
    const float4* r4 = (const float4*)(dptr + at * SS);

    float mn = BIGV;
    #pragma unroll
    for (int j = 0; j < 8; j++) {
        float4 q = __ldg(&r4[ac * 8 + j]);
        mn = fminf(mn, fminf(fminf(q.x, q.y), fminf(q.z, q.w)));
    }
    float tau = mn;    // max over the 8 chunk-mins of this t
    tau = fmaxf(tau, __shfl_xor_sync(0xffffffffu, tau, 1));
    tau = fmaxf(tau, __shfl_xor_sync(0xffffffffu, tau, 2));
    tau = fmaxf(tau, __shfl_xor_sync(0xffffffffu, tau, 4));
    // >= 8 candidates per t are <= tau.

    {
        int cnt = 0;
        float*          pv = &poolv [at * PVS + ac * CAP];
        unsigned short* ps = &poolsb[at * PSS + ac * CAP];
        #pragma unroll
        for (int j = 0; j < 8; j++) {
            float4 q = __ldg(&r4[ac * 8 + j]);   // L1 hit (re-read)
            int s = ac * 32 + j * 4;
            if (q.x <= tau) { if (cnt < CAP) { pv[cnt] = q.x;
                ps[cnt] = (unsigned short)((s+0) | (mnib[s+0] << 8)); } cnt++; }
            if (q.y <= tau) { if (cnt < CAP) { pv[cnt] = q.y;
                ps[cnt] = (unsigned short)((s+1) | (mnib[s+1] << 8)); } cnt++; }
            if (q.z <= tau) { if (cnt < CAP) { pv[cnt] = q.z;
                ps[cnt] = (unsigned short)((s+2) | (mnib[s+2] << 8)); } cnt++; }
            if (q.w <= tau) { if (cnt < CAP) { pv[cnt] = q.w;
                ps[cnt] = (unsigned short)((s+3) | (mnib[s+3] << 8)); } cnt++; }
        }
        cnts[at * 8 + ac] = (unsigned char)cnt;
    }
    __syncthreads();

    // ================= Phase B: exact top-3 over the pool =================
    const int nv = tid & 3;
    const int ph = (tid >> 2) & 1;
    const int t  = tid >> 3;                 // == at, tau valid for this t

    float a0 = BIGV, a1 = BIGV, a2 = BIGV;
    int   ai0 = BIGI, ai1 = BIGI, ai2 = BIGI;
    int ovf = 0;

    const float*          pvb = &poolv [t * PVS];
    const unsigned short* psb = &poolsb[t * PSS];

    #pragma unroll
    for (int c = 0; c < 8; c++) {
        int n = cnts[t * 8 + c];
        if (n > CAP) { ovf = 1; n = CAP; }
        const int base = c * CAP;
        for (int i = ph; i < n; i += 2) {
            float v          = pvb[base + i];
            unsigned short w = psb[base + i];
            int s = w & 255;
            if (!((w >> (8 + nv)) & 1))
                top3_insert_vi(v, s, a0, a1, a2, ai0, ai1, ai2);
        }
    }

    // merge the two ph lanes (partner = lane ^ 4) — all shfls unconditional
    {
        float ov0 = __shfl_xor_sync(0xffffffffu, a0, 4);
        float ov1 = __shfl_xor_sync(0xffffffffu, a1, 4);
        float ov2 = __shfl_xor_sync(0xffffffffu, a2, 4);
        int   oi0 = __shfl_xor_sync(0xffffffffu, ai0, 4);
        int   oi1 = __shfl_xor_sync(0xffffffffu, ai1, 4);
        int   oi2 = __shfl_xor_sync(0xffffffffu, ai2, 4);
        top3_insert_vi(ov0, oi0, a0, a1, a2, ai0, ai1, ai2);
        top3_insert_vi(ov1, oi1, a0, a1, a2, ai0, ai1, ai2);
        top3_insert_vi(ov2, oi2, a0, a1, a2, ai0, ai1, ai2);
    }
    int ovf_other = __shfl_xor_sync(0xffffffffu, ovf, 4);   // never short-circuit a shfl
    int ovf2 = ovf | ovf_other;

    // exactness: excluded unmasked sources have dist > tau; masked ones have
    // value >= 1e6 > tau. So a2 <= tau (and no overflow) proves exactness.
    bool flag = (ovf2 != 0) || (a2 > tau);
    if (__any_sync(0xffffffffu, flag)) {
        // rare exact fallback: full rescan with reference semantics
        const float* rowf = dptr + t * SS;
        float f0 = BIGV, f1 = BIGV, f2 = BIGV;
        int   g0 = BIGI, g1 = BIGI, g2 = BIGI;
        for (int k = 0; k < 128; k++) {
            int s = (k << 1) | ph;
            float pen = ((mnib[s] >> nv) & 1) ? MASKVAL : 0.0f;
            float v = __ldg(&rowf[s]) + pen;
            top3_insert_vi(v, s, f0, f1, f2, g0, g1, g2);
        }
        float ov0 = __shfl_xor_sync(0xffffffffu, f0, 4);
        float ov1 = __shfl_xor_sync(0xffffffffu, f1, 4);
        float ov2 = __shfl_xor_sync(0xffffffffu, f2, 4);
        int   oi0 = __shfl_xor_sync(0xffffffffu, g0, 4);
        int   oi1 = __shfl_xor_sync(0xffffffffu, g1, 4);
        int   oi2 = __shfl_xor_sync(0xffffffffu, g2, 4);
        top3_insert_vi(ov0, oi0, f0, f1, f2, g0, g1, g2);
        top3_insert_vi(ov1, oi1, f0, f1, f2, g0, g1, g2);
        top3_insert_vi(ov2, oi2, f0, f1, f2, g0, g1, g2);
        if (flag) {
            a0 = f0; a1 = f1; a2 = f2;
            ai0 = g0; ai1 = g1; ai2 = g2;
        }
    }

    // ---- weights ----
    float q0 = fmaxf(a0, CUTOFF);
    float q1 = fmaxf(a1, CUTOFF);
    float q2 = fmaxf(a2, CUTOFF);
    float w0 = 1.0f / (q0 * q0);
    float w1 = 1.0f / (q1 * q1);
    float w2 = 1.0f / (q2 * q2);
    float inv = 1.0f / (w0 + w1 + w2);
    w0 *= inv; w1 *= inv; w2 *= inv;

    // ---- gather + blend: each ph lane writes 2 of the 4 float4s ----
    const int tg = t + tb * 32;              // global target 0..63
    const float* xb = x + ((size_t)((b * NTT + nt) * NLG + l)) * SS * NVV * FF;
    const float4* p0 = (const float4*)(xb + ((size_t)ai0 * NVV + nv) * FF);
    const float4* p1 = (const float4*)(xb + ((size_t)ai1 * NVV + nv) * FF);
    const float4* p2 = (const float4*)(xb + ((size_t)ai2 * NVV + nv) * FF);

    const size_t row = (size_t)((b * NTT + nt) * (NLG * TT)) + (size_t)l * TT + tg;
    float4* op = (float4*)(out + (row * NVV + nv) * FF);

    const int j0 = ph * 2;
    #pragma unroll
    for (int j = j0; j < j0 + 2; j++) {
        float4 va = p0[j], vb = p1[j], vc = p2[j];
        float4 r;
        r.x = w0 * va.x + w1 * vb.x + w2 * vc.x;
        r.y = w0 * va.y + w1 * vb.y + w2 * vc.y;
        r.z = w0 * va.z + w1 * vb.z + w2 * vc.z;
        r.w = w0 * va.w + w1 * vb.w + w2 * vc.w;
        op[j] = r;
    }

    // ---- dist_vals output: split between the two ph lanes ----
    const size_t XSZ = (size_t)NB * NTT * NLG * TT * NVV * FF;  // 4,194,304
    size_t dbase = XSZ + (row * KNN) * NVV + nv;
    if (ph == 0) {
        out[dbase]       = q0;
        out[dbase + NVV] = q1;
    } else {
        out[dbase + 2 * NVV] = q2;
    }
}

extern "C" void kernel_launch(void* const* d_in, const int* in_sizes, int n_in,
                              void* d_out, int out_size) {
    const float* x    = (const float*)d_in[0];
    const void*  mask = (const void*)d_in[1];
    const float* dist = (const float*)d_in[2];
    float*       out  = (float*)d_out;

    interp_kernel<<<NB * NTT * NLG * 2, 256>>>(x, mask, dist, out);
}

// round 9
// speedup vs baseline: 1.3840x; 1.3840x over previous
#include <cuda_runtime.h>
#include <cstdint>

#define NB    2
#define NTT   2
#define NLG   256
#define TT    64
#define SS    256
#define NVV   4
#define FF    16
#define KNN   3
#define CUTOFF   1e-3f
#define MASKVAL  1e6f

#define RCAP  64            // per-row pool capacity
#define BIGV 3.4e38f
#define BIGI 0x3fffffff

__device__ __forceinline__ bool lessvi(float v, int i, float w, int j) {
    return (v < w) || (v == w && i < j);
}

// exact lexicographic (value, index) top-3 insert
__device__ __forceinline__ void top3_insert_vi(float v, int s,
                                               float& d0, float& d1, float& d2,
                                               int& i0, int& i1, int& i2) {
    if (lessvi(v, s, d2, i2)) {
        if (lessvi(v, s, d1, i1)) {
            d2 = d1; i2 = i1;
            if (lessvi(v, s, d0, i0)) { d1 = d0; i1 = i0; d0 = v; i0 = s; }
            else                      { d1 = v;  i1 = s; }
        } else {
            d2 = v; i2 = s;
        }
    }
}

__global__ __launch_bounds__(256, 5) void interp_kernel(
    const float* __restrict__ x,            // (B,NT, NL*S, NV, F)
    const void*  __restrict__ mask_raw,     // (B,NT, NL*S, NV) — dtype detected
    const float* __restrict__ dist,         // (B, NL, T, S)
    float* __restrict__ out)
{
    __shared__ float          poolv[32 * RCAP];    // 8 KB candidate values
    __shared__ unsigned short pools[32 * RCAP];    // 4 KB  s | nibble<<8
    __shared__ float          staus[32];           // per-row tau
    __shared__ int            cnts [32];           // raw survivor counts
    __shared__ unsigned char  mnib [SS];           // mask nibbles per s
    __shared__ int s_flags[2];

    const int bid   = blockIdx.x;
    const int tb    = bid & 1;               // half of the 64 targets
    const int group = bid >> 1;
    const int l     = group & 255;
    const int nt    = (group >> 8) & 1;
    const int b     = group >> 9;
    const int tid   = threadIdx.x;
    const int wid   = tid >> 5;
    const int lane  = tid & 31;

    if (tid == 0) { s_flags[0] = 0; s_flags[1] = 0; }
    __syncthreads();

    // ---- mask dtype detection from first 1024 bytes ----
    {
        const uchar4* mb = (const uchar4*)mask_raw;
        uchar4 q = mb[tid];
        int u8  = (q.y == 1) | (q.z == 1) | (q.w == 1);
        int f32 = (q.x == 0x3F) | (q.y == 0x3F) | (q.z == 0x3F) | (q.w == 0x3F);
        if (u8)  atomicOr(&s_flags[0], 1);
        if (f32) atomicOr(&s_flags[1], 1);
    }
    __syncthreads();
    const int mkind = s_flags[0] ? 0 : (s_flags[1] ? 2 : 1);

    // ---- stage mask -> nibble table mnib[s] (tid = s), bit nv = masked ----
    {
        const size_t moff = ((size_t)((b * NTT + nt) * NLG + l)) * SS * NVV;
        int nib;
        if (mkind == 0) {
            const uchar4* msrc = (const uchar4*)((const unsigned char*)mask_raw + moff);
            uchar4 m = msrc[tid];
            nib = (m.x ? 1 : 0) | (m.y ? 2 : 0) | (m.z ? 4 : 0) | (m.w ? 8 : 0);
        } else if (mkind == 1) {
            const int4* msrc = (const int4*)((const int*)mask_raw + moff);
            int4 m = msrc[tid];
            nib = (m.x ? 1 : 0) | (m.y ? 2 : 0) | (m.z ? 4 : 0) | (m.w ? 8 : 0);
        } else {
            const float4* msrc = (const float4*)((const float*)mask_raw + moff);
            float4 m = msrc[tid];
            nib = (m.x != 0.0f ? 1 : 0) | (m.y != 0.0f ? 2 : 0) |
                  (m.z != 0.0f ? 4 : 0) | (m.w != 0.0f ? 8 : 0);
        }
        mnib[tid] = (unsigned char)nib;
    }
    __syncthreads();

    // ============ Phase A: per-warp, 4 rows, registers only ============
    const float* dbase = dist + (((size_t)(b * NLG + l)) * TT + tb * 32) * SS;
    const unsigned lmlt = (1u << lane) - 1u;

    #pragma unroll
    for (int r = 0; r < 4; r++) {
        const int t = wid * 4 + r;
        const float4* row = (const float4*)(dbase + (size_t)t * SS);
        float4 v1 = __ldg(&row[lane]);        // s = 4*lane + j
        float4 v2 = __ldg(&row[lane + 32]);   // s = 128 + 4*lane + j

        // chunk = s>>5; v1 covers chunk lane>>3, v2 covers 4 + lane>>3
        float m1 = fminf(fminf(v1.x, v1.y), fminf(v1.z, v1.w));
        float m2 = fminf(fminf(v2.x, v2.y), fminf(v2.z, v2.w));
        m1 = fminf(m1, __shfl_xor_sync(0xffffffffu, m1, 1));
        m1 = fminf(m1, __shfl_xor_sync(0xffffffffu, m1, 2));
        m1 = fminf(m1, __shfl_xor_sync(0xffffffffu, m1, 4));
        m2 = fminf(m2, __shfl_xor_sync(0xffffffffu, m2, 1));
        m2 = fminf(m2, __shfl_xor_sync(0xffffffffu, m2, 2));
        m2 = fminf(m2, __shfl_xor_sync(0xffffffffu, m2, 4));
        float mx = fmaxf(m1, m2);
        mx = fmaxf(mx, __shfl_xor_sync(0xffffffffu, mx, 8));
        mx = fmaxf(mx, __shfl_xor_sync(0xffffffffu, mx, 16));
        const float tau = mx;                 // >=8 candidates <= tau
        if (lane == 0) staus[t] = tau;

        // ballot compaction of (value, s|nib) into the row pool
        float*          pv = &poolv[t * RCAP];
        unsigned short* ps = &pools[t * RCAP];
        int base = 0;

        #define EMIT(VAL, SIDX)                                              \
        {                                                                    \
            bool p = ((VAL) <= tau);                                         \
            unsigned bal = __ballot_sync(0xffffffffu, p);                    \
            int idx = base + __popc(bal & lmlt);                             \
            if (p && idx < RCAP) {                                           \
                pv[idx] = (VAL);                                             \
                ps[idx] = (unsigned short)((SIDX) | (mnib[(SIDX)] << 8));    \
            }                                                                \
            base += __popc(bal);                                             \
        }
        EMIT(v1.x, 4 * lane + 0)
        EMIT(v1.y, 4 * lane + 1)
        EMIT(v1.z, 4 * lane + 2)
        EMIT(v1.w, 4 * lane + 3)
        EMIT(v2.x, 128 + 4 * lane + 0)
        EMIT(v2.y, 128 + 4 * lane + 1)
        EMIT(v2.z, 128 + 4 * lane + 2)
        EMIT(v2.w, 128 + 4 * lane + 3)
        #undef EMIT

        if (lane == 0) cnts[t] = base;
    }
    __syncwarp();   // pools/cnts/staus for t in [4*wid, 4*wid+4) are warp-local

    // ============ Phase B: exact top-3 over the pool ============
    const int nv = tid & 3;
    const int ph = (tid >> 2) & 1;
    const int t  = tid >> 3;                  // in [4*wid, 4*wid+4) ✓ same warp

    const float tau = staus[t];
    const int   raw = cnts[t];
    const int   n   = raw > RCAP ? RCAP : raw;
    const int   ovf = raw > RCAP;

    float a0 = BIGV, a1 = BIGV, a2 = BIGV;
    int   ai0 = BIGI, ai1 = BIGI, ai2 = BIGI;

    const float*          pv = &poolv[t * RCAP];
    const unsigned short* ps = &pools[t * RCAP];
    for (int i = ph; i < n; i += 2) {
        float v          = pv[i];
        unsigned short w = ps[i];
        int s = w & 255;
        if (!((w >> (8 + nv)) & 1))
            top3_insert_vi(v, s, a0, a1, a2, ai0, ai1, ai2);
    }

    // merge the two ph lanes (partner = lane ^ 4) — shfls unconditional
    {
        float ov0 = __shfl_xor_sync(0xffffffffu, a0, 4);
        float ov1 = __shfl_xor_sync(0xffffffffu, a1, 4);
        float ov2 = __shfl_xor_sync(0xffffffffu, a2, 4);
        int   oi0 = __shfl_xor_sync(0xffffffffu, ai0, 4);
        int   oi1 = __shfl_xor_sync(0xffffffffu, ai1, 4);
        int   oi2 = __shfl_xor_sync(0xffffffffu, ai2, 4);
        top3_insert_vi(ov0, oi0, a0, a1, a2, ai0, ai1, ai2);
        top3_insert_vi(ov1, oi1, a0, a1, a2, ai0, ai1, ai2);
        top3_insert_vi(ov2, oi2, a0, a1, a2, ai0, ai1, ai2);
    }

    // exactness: excluded unmasked sources have dist > tau; masked pooled
    // entries are skipped identically to +1e6 (>= tau). a2 <= tau + !ovf => exact.
    bool flag = ovf || (a2 > tau);
    if (__any_sync(0xffffffffu, flag)) {
        const float* rowf = dbase + (size_t)t * SS;
        float f0 = BIGV, f1 = BIGV, f2 = BIGV;
        int   g0 = BIGI, g1 = BIGI, g2 = BIGI;
        for (int k = 0; k < 128; k++) {
            int s = (k << 1) | ph;
            float pen = ((mnib[s] >> nv) & 1) ? MASKVAL : 0.0f;
            float v = __ldg(&rowf[s]) + pen;
            top3_insert_vi(v, s, f0, f1, f2, g0, g1, g2);
        }
        float ov0 = __shfl_xor_sync(0xffffffffu, f0, 4);
        float ov1 = __shfl_xor_sync(0xffffffffu, f1, 4);
        float ov2 = __shfl_xor_sync(0xffffffffu, f2, 4);
        int   oi0 = __shfl_xor_sync(0xffffffffu, g0, 4);
        int   oi1 = __shfl_xor_sync(0xffffffffu, g1, 4);
        int   oi2 = __shfl_xor_sync(0xffffffffu, g2, 4);
        top3_insert_vi(ov0, oi0, f0, f1, f2, g0, g1, g2);
        top3_insert_vi(ov1, oi1, f0, f1, f2, g0, g1, g2);
        top3_insert_vi(ov2, oi2, f0, f1, f2, g0, g1, g2);
        if (flag) {
            a0 = f0; a1 = f1; a2 = f2;
            ai0 = g0; ai1 = g1; ai2 = g2;
        }
    }

    // ---- weights ----
    float q0 = fmaxf(a0, CUTOFF);
    float q1 = fmaxf(a1, CUTOFF);
    float q2 = fmaxf(a2, CUTOFF);
    float w0 = 1.0f / (q0 * q0);
    float w1 = 1.0f / (q1 * q1);
    float w2 = 1.0f / (q2 * q2);
    float inv = 1.0f / (w0 + w1 + w2);
    w0 *= inv; w1 *= inv; w2 *= inv;

    // ---- gather + blend: each ph lane writes 2 of the 4 float4s ----
    const int tg = t + tb * 32;               // global target 0..63
    const float* xb = x + ((size_t)((b * NTT + nt) * NLG + l)) * SS * NVV * FF;
    const float4* p0 = (const float4*)(xb + ((size_t)ai0 * NVV + nv) * FF);
    const float4* p1 = (const float4*)(xb + ((size_t)ai1 * NVV + nv) * FF);
    const float4* p2 = (const float4*)(xb + ((size_t)ai2 * NVV + nv) * FF);

    const size_t row = (size_t)((b * NTT + nt) * (NLG * TT)) + (size_t)l * TT + tg;
    float4* op = (float4*)(out + (row * NVV + nv) * FF);

    const int j0 = ph * 2;
    #pragma unroll
    for (int j = j0; j < j0 + 2; j++) {
        float4 va = p0[j], vb = p1[j], vc = p2[j];
        float4 rr;
        rr.x = w0 * va.x + w1 * vb.x + w2 * vc.x;
        rr.y = w0 * va.y + w1 * vb.y + w2 * vc.y;
        rr.z = w0 * va.z + w1 * vb.z + w2 * vc.z;
        rr.w = w0 * va.w + w1 * vb.w + w2 * vc.w;
        op[j] = rr;
    }

    // ---- dist_vals output: split between the two ph lanes ----
    const size_t XSZ = (size_t)NB * NTT * NLG * TT * NVV * FF;  // 4,194,304
    size_t dbaseo = XSZ + (row * KNN) * NVV + nv;
    if (ph == 0) {
        out[dbaseo]       = q0;
        out[dbaseo + NVV] = q1;
    } else {
        out[dbaseo + 2 * NVV] = q2;
    }
}

extern "C" void kernel_launch(void* const* d_in, const int* in_sizes, int n_in,
                              void* d_out, int out_size) {
    const float* x    = (const float*)d_in[0];
    const void*  mask = (const void*)d_in[1];
    const float* dist = (const float*)d_in[2];
    float*       out  = (float*)d_out;

    interp_kernel<<<NB * NTT * NLG * 2, 256>>>(x, mask, dist, out);
}